// round 2
// baseline (speedup 1.0000x reference)
#include <cuda_runtime.h>
#include <math.h>

#define P 128
#define NP 16384          // 128*128
#define KB 6
#define PLANE 262144      // 512*512

// ---------------- scratch (static device globals; no allocation) -------------
__device__ int   g_box[2];                     // y1, x1
__device__ float g_feat_patch[KB*64*NP];       // 25 MB
__device__ float g_x_patch[KB*3*NP];
__device__ float g_pred_patch[KB*3*NP];
__device__ float g_fs[KB*96*NP];               // 37.7 MB
__device__ float g_S0[32*NP];
__device__ float g_S1[32*NP];
__device__ float g_M2[32*NP];
__device__ float g_h1[KB*64*NP];
__device__ float g_fm[KB*64*NP];

// ---------------- box computation -------------------------------------------
__global__ void box_kernel(const float* __restrict__ pred) {
    __shared__ float svals[1024];
    __shared__ int   sidx[1024];
    const int t = threadIdx.x;
    float best = -1e30f; int bidx = 0;
    for (int i = t; i < 51*51; i += 1024) {
        int iy = i / 51, ix = i % 51;
        int y = iy * 10, x = ix * 10;
        float T = 0.f, Bm = 0.f;
        for (int k = 0; k < KB; k++) {
            const float* pk = pred + (size_t)k * 3 * PLANE + y * 512 + x;
            T  += pk[0];          // channel 0
            Bm += pk[2*PLANE];    // channel 2
        }
        float d = fabsf(1.0f - T - Bm / 6.0f);
        if (d > best) { best = d; bidx = i; }   // strict > keeps first occurrence
    }
    svals[t] = best; sidx[t] = bidx;
    __syncthreads();
    for (int s = 512; s > 0; s >>= 1) {
        if (t < s) {
            if (svals[t+s] > svals[t] ||
                (svals[t+s] == svals[t] && sidx[t+s] < sidx[t])) {
                svals[t] = svals[t+s]; sidx[t] = sidx[t+s];
            }
        }
        __syncthreads();
    }
    if (t == 0) {
        int idx = sidx[0];
        int cx = (idx % 51) * 10, cy = (idx / 51) * 10;
        int x1 = cx - 64, y1 = cy - 64, x2 = cx + 64, y2 = cy + 64;
        int ox = -min(x1,0) + min(512 - x1, 0) - min(x2,0) + min(512 - x2, 0);
        int oy = -min(y1,0) + min(512 - y1, 0) - min(y2,0) + min(512 - y2, 0);
        g_box[0] = y1 + oy; g_box[1] = x1 + ox;
    }
}

// ---------------- copy pred->out + extract x/feat patches --------------------
__global__ void prep_kernel(const float* __restrict__ x,
                            const float* __restrict__ pred,
                            const float* __restrict__ feat,
                            float* __restrict__ out) {
    const int y1 = g_box[0], x1 = g_box[1];
    const int N1 = KB*3*PLANE;
    const int N2 = KB*3*NP;
    const int N3 = KB*64*NP;
    const int total = N1 + N2 + N3;
    for (int i = blockIdx.x * blockDim.x + threadIdx.x; i < total;
         i += gridDim.x * blockDim.x) {
        if (i < N1) {
            out[i] = pred[i];
        } else if (i < N1 + N2) {
            int j = i - N1;
            int kc = j / NP;
            int p  = j % NP;
            int yy = p >> 7, xx = p & 127;
            g_x_patch[j] = x[(size_t)kc * PLANE + (y1+yy)*512 + (x1+xx)];
        } else {
            int j = i - N1 - N2;
            int kc = j / NP;
            int p  = j % NP;
            int yy = p >> 7, xx = p & 127;
            g_feat_patch[j] = feat[(size_t)kc * PLANE + (y1+yy)*512 + (x1+xx)];
        }
    }
}

__global__ void extract_pred_kernel(const float* __restrict__ out) {
    int i = blockIdx.x * blockDim.x + threadIdx.x;
    if (i >= KB*3*NP) return;
    const int y1 = g_box[0], x1 = g_box[1];
    int kc = i / NP;
    int p  = i % NP;
    int yy = p >> 7, xx = p & 127;
    g_pred_patch[i] = out[(size_t)kc * PLANE + (y1+yy)*512 + (x1+xx)];
}

// ---------------- input loader modes -----------------------------------------
// MODE 0: plain NCHW load       MODE 1: load * attention (staged separately)
// MODE 2: fcat on-the-fly (merge1 input: [feat_t|feat_r|feat_b|x_patch])
template<int MODE>
__device__ __forceinline__ float load_in(const float* __restrict__ in_base,
                                         int k, int cg, int gy, int gx) {
    int p = gy*P + gx;
    if (MODE == 2) {
        const float* f = in_base;              // g_fs + k*96*NP
        if (cg < 32) {
            return g_S1[cg*NP + p] / 5.0f - g_S0[cg*NP + p] + 2.0f * f[cg*NP + p];
        } else if (cg < 64) {
            int c = cg - 32;
            return g_S0[c*NP + p] - f[c*NP + p] + f[(32+c)*NP + p];
        } else if (cg < 96) {
            return g_M2[(cg-64)*NP + p];
        } else {
            return g_x_patch[(k*3 + (cg-96))*NP + p];
        }
    }
    return in_base[cg*NP + p];
}

// ---------------- register-tiled 3x3 conv body -------------------------------
// Tile: 16 wide x 8 tall. Thread = 2x2 pixels x OCPT out channels.
// blockDim = (32, COUT/OCPT)
template<int CIN, int COUT, int OCPT, bool RELU, int MODE>
__device__ __forceinline__ void conv3x3_body(
    const float* __restrict__ in_base, int k,
    const float* __restrict__ att,
    const float* __restrict__ W,
    const float* __restrict__ Bv,
    float* __restrict__ out_base)
{
    constexpr int NOCG = COUT / OCPT;
    constexpr int NTHR = 32 * NOCG;
    constexpr int CCH = 8;
    __shared__ float in_s[CCH][10][20];       // 18 valid cols, stride 20
    __shared__ float w_s[COUT][CCH*9];        // broadcast-read layout
    __shared__ float att_s[10][20];

    const int x0 = blockIdx.x * 16;
    const int y0 = blockIdx.y * 8;
    const int tid = threadIdx.y * 32 + threadIdx.x;
    const int tx = (threadIdx.x & 7) * 2;
    const int ty = (threadIdx.x >> 3) * 2;
    const int ocb = threadIdx.y * OCPT;

    if (MODE == 1) {
        for (int i = tid; i < 180; i += NTHR) {
            int ly = i / 18, lx = i % 18;
            int gy = y0 + ly - 1, gx = x0 + lx - 1;
            att_s[ly][lx] = (gy >= 0 && gy < P && gx >= 0 && gx < P)
                                ? att[gy*P + gx] : 0.f;
        }
    }

    float acc[2][2][OCPT];
    #pragma unroll
    for (int a = 0; a < 2; a++)
        #pragma unroll
        for (int b = 0; b < 2; b++)
            #pragma unroll
            for (int j = 0; j < OCPT; j++) acc[a][b][j] = 0.f;

    for (int c0 = 0; c0 < CIN; c0 += CCH) {
        __syncthreads();
        for (int i = tid; i < CCH*180; i += NTHR) {
            int c = i / 180, r = i % 180;
            int ly = r / 18, lx = r % 18;
            int gy = y0 + ly - 1, gx = x0 + lx - 1;
            int cg = c0 + c;
            float v = 0.f;
            if (cg < CIN && gy >= 0 && gy < P && gx >= 0 && gx < P) {
                v = load_in<MODE>(in_base, k, cg, gy, gx);
                if (MODE == 1) v *= att_s[ly][lx];
            }
            in_s[c][ly][lx] = v;
        }
        for (int i = tid; i < COUT*CCH*9; i += NTHR) {
            int o = i / (CCH*9), r = i % (CCH*9);
            int cg = c0 + r / 9, kk = r % 9;
            w_s[o][r] = (cg < CIN) ? W[(o*CIN + cg)*9 + kk] : 0.f;
        }
        __syncthreads();
        #pragma unroll 1
        for (int c = 0; c < CCH; c++) {
            float v[4][4];
            #pragma unroll
            for (int dy = 0; dy < 4; dy++)
                #pragma unroll
                for (int dx = 0; dx < 4; dx++)
                    v[dy][dx] = in_s[c][ty+dy][tx+dx];
            #pragma unroll
            for (int kk = 0; kk < 9; kk++) {
                const int ky = kk / 3, kx = kk % 3;
                float wv[OCPT];
                #pragma unroll
                for (int j = 0; j < OCPT; j++) wv[j] = w_s[ocb+j][c*9+kk];
                #pragma unroll
                for (int py = 0; py < 2; py++)
                    #pragma unroll
                    for (int qx = 0; qx < 2; qx++) {
                        float iv = v[py+ky][qx+kx];
                        #pragma unroll
                        for (int j = 0; j < OCPT; j++)
                            acc[py][qx][j] = fmaf(iv, wv[j], acc[py][qx][j]);
                    }
            }
        }
    }
    #pragma unroll
    for (int j = 0; j < OCPT; j++) {
        int o = ocb + j;
        float b = Bv[o];
        #pragma unroll
        for (int py = 0; py < 2; py++)
            #pragma unroll
            for (int qx = 0; qx < 2; qx++) {
                float r = acc[py][qx][j] + b;
                if (RELU) r = (r >= 0.f) ? r : 0.2f * r;
                out_base[o*NP + (y0+ty+py)*P + (x0+tx+qx)] = r;
            }
    }
}

__global__ void __launch_bounds__(128)
split_conv_kernel(const float* __restrict__ W, const float* __restrict__ Bv) {
    int z = blockIdx.z; int k = z / 3, g = z - 3*k;
    conv3x3_body<64, 32, 8, false, 1>(
        g_feat_patch + k*64*NP, k,
        g_pred_patch + (k*3 + g)*NP,
        W + g*32*64*9,
        Bv + g*32,
        g_fs + (k*96 + g*32)*NP);
}

__global__ void __launch_bounds__(256)
merge1_kernel(const float* __restrict__ W, const float* __restrict__ Bv) {
    int k = blockIdx.z;
    conv3x3_body<99, 64, 8, true, 2>(
        g_fs + k*96*NP, k, nullptr, W, Bv, g_h1 + k*64*NP);
}

__global__ void __launch_bounds__(256)
merge2_kernel(const float* __restrict__ W, const float* __restrict__ Bv) {
    int k = blockIdx.z;
    conv3x3_body<64, 64, 8, false, 0>(
        g_h1 + k*64*NP, k, nullptr, W, Bv, g_fm + k*64*NP);
}

// ---------------- K-reduction of fs ------------------------------------------
__global__ void reduce_kernel() {
    int i = blockIdx.x * blockDim.x + threadIdx.x;
    if (i >= 32*NP) return;
    int c = i / NP, p = i % NP;
    float s0 = 0.f, s1 = 0.f, s2 = 0.f;
    #pragma unroll
    for (int k = 0; k < KB; k++) {
        const float* f = g_fs + k*96*NP;
        s0 += f[c*NP + p];
        s1 += f[(32+c)*NP + p];
        s2 += f[(64+c)*NP + p];
    }
    g_S0[i] = s0; g_S1[i] = s1; g_M2[i] = s2 / 6.0f;
}

// ---------------- head conv + tanh + scatter ---------------------------------
__global__ void __launch_bounds__(256)
head_kernel(const float* __restrict__ W, const float* __restrict__ Bv,
            float* __restrict__ out) {
    __shared__ float in_s[8][18][20];
    __shared__ float w_s[3][72];
    const int k = blockIdx.z;
    const float* fm = g_fm + k*64*NP;
    const int x0 = blockIdx.x * 16, y0 = blockIdx.y * 16;
    const int tid = threadIdx.y * 16 + threadIdx.x;
    float acc[3] = {0.f, 0.f, 0.f};
    for (int c0 = 0; c0 < 64; c0 += 8) {
        __syncthreads();
        for (int i = tid; i < 8*18*18; i += 256) {
            int c = i / 324, r = i % 324, ly = r / 18, lx = r % 18;
            int gy = y0 + ly - 1, gx = x0 + lx - 1;
            in_s[c][ly][lx] = (gy >= 0 && gy < P && gx >= 0 && gx < P)
                                  ? fm[(c0+c)*NP + gy*P + gx] : 0.f;
        }
        for (int i = tid; i < 3*72; i += 256) {
            int o = i / 72, r = i % 72;
            int c = r / 9, kk = r % 9;
            w_s[o][r] = W[(o*64 + c0 + c)*9 + kk];
        }
        __syncthreads();
        #pragma unroll 1
        for (int c = 0; c < 8; c++) {
            #pragma unroll
            for (int kk = 0; kk < 9; kk++) {
                float v = in_s[c][threadIdx.y + kk/3][threadIdx.x + kk%3];
                #pragma unroll
                for (int o = 0; o < 3; o++)
                    acc[o] = fmaf(v, w_s[o][c*9+kk], acc[o]);
            }
        }
    }
    int y = y0 + threadIdx.y, x = x0 + threadIdx.x;
    if (y >= 10 && y < 118 && x >= 10 && x < 118) {
        int y1 = g_box[0], x1 = g_box[1];
        #pragma unroll
        for (int o = 0; o < 3; o++) {
            float val = 0.5f * (tanhf(acc[o] + Bv[o]) + 1.0f);
            out[(size_t)(k*3 + o) * PLANE + (y1+y)*512 + (x1+x)] = val;
        }
    }
}

// ---------------- launch -----------------------------------------------------
extern "C" void kernel_launch(void* const* d_in, const int* in_sizes, int n_in,
                              void* d_out, int out_size) {
    const float* x       = (const float*)d_in[0];
    const float* pred    = (const float*)d_in[1];
    const float* feat    = (const float*)d_in[2];
    const float* split_w = (const float*)d_in[3];
    const float* split_b = (const float*)d_in[4];
    const float* m1w     = (const float*)d_in[5];
    const float* m1b     = (const float*)d_in[6];
    const float* m2w     = (const float*)d_in[7];
    const float* m2b     = (const float*)d_in[8];
    const float* hw      = (const float*)d_in[9];
    const float* hb      = (const float*)d_in[10];
    float* out = (float*)d_out;

    box_kernel<<<1, 1024>>>(pred);
    prep_kernel<<<8192, 256>>>(x, pred, feat, out);

    dim3 gridM(8, 16, KB),   blkM(32, 8);
    dim3 gridS(8, 16, KB*3), blkS(32, 4);
    dim3 gridH(8, 8, KB),    blkH(16, 16);

    for (int it = 0; it < 2; it++) {
        extract_pred_kernel<<<(KB*3*NP + 255)/256, 256>>>(out);
        split_conv_kernel<<<gridS, blkS>>>(split_w, split_b);
        reduce_kernel<<<(32*NP + 255)/256, 256>>>();
        merge1_kernel<<<gridM, blkM>>>(m1w, m1b);
        merge2_kernel<<<gridM, blkM>>>(m2w, m2b);
        head_kernel<<<gridH, blkH>>>(hw, hb, out);
    }
}

// round 3
// speedup vs baseline: 1.2732x; 1.2732x over previous
#include <cuda_runtime.h>
#include <math.h>

#define P 128
#define NP 16384          // 128*128
#define KB 6
#define PLANE 262144      // 512*512

// ---------------- scratch (static device globals; no allocation) -------------
__device__ int   g_box[2];                     // y1, x1
__device__ float g_feat_patch[KB*64*NP];
__device__ float g_x_patch[KB*3*NP];
__device__ float g_pred_patch[KB*3*NP];
__device__ float g_fs[KB*96*NP];
__device__ float g_S0[32*NP];
__device__ float g_S1[32*NP];
__device__ float g_M2[32*NP];
__device__ float g_h1[KB*64*NP];
__device__ float g_fm[KB*64*NP];

// ---------------- packed f32x2 helpers ---------------------------------------
__device__ __forceinline__ unsigned long long dup2(float v) {
    unsigned long long r;
    asm("mov.b64 %0, {%1, %1};" : "=l"(r) : "f"(v));
    return r;
}
__device__ __forceinline__ void fma2(unsigned long long& d,
                                     unsigned long long a,
                                     unsigned long long b) {
    asm("fma.rn.f32x2 %0, %1, %2, %0;" : "+l"(d) : "l"(a), "l"(b));
}
__device__ __forceinline__ float2 unpack2(unsigned long long v) {
    float2 f;
    asm("mov.b64 {%0, %1}, %2;" : "=f"(f.x), "=f"(f.y) : "l"(v));
    return f;
}

// ---------------- box computation -------------------------------------------
__global__ void box_kernel(const float* __restrict__ pred) {
    __shared__ float svals[1024];
    __shared__ int   sidx[1024];
    const int t = threadIdx.x;
    float best = -1e30f; int bidx = 0;
    for (int i = t; i < 51*51; i += 1024) {
        int iy = i / 51, ix = i % 51;
        int y = iy * 10, x = ix * 10;
        float T = 0.f, Bm = 0.f;
        for (int k = 0; k < KB; k++) {
            const float* pk = pred + (size_t)k * 3 * PLANE + y * 512 + x;
            T  += pk[0];
            Bm += pk[2*PLANE];
        }
        float d = fabsf(1.0f - T - Bm / 6.0f);
        if (d > best) { best = d; bidx = i; }
    }
    svals[t] = best; sidx[t] = bidx;
    __syncthreads();
    for (int s = 512; s > 0; s >>= 1) {
        if (t < s) {
            if (svals[t+s] > svals[t] ||
                (svals[t+s] == svals[t] && sidx[t+s] < sidx[t])) {
                svals[t] = svals[t+s]; sidx[t] = sidx[t+s];
            }
        }
        __syncthreads();
    }
    if (t == 0) {
        int idx = sidx[0];
        int cx = (idx % 51) * 10, cy = (idx / 51) * 10;
        int x1 = cx - 64, y1 = cy - 64, x2 = cx + 64, y2 = cy + 64;
        int ox = -min(x1,0) + min(512 - x1, 0) - min(x2,0) + min(512 - x2, 0);
        int oy = -min(y1,0) + min(512 - y1, 0) - min(y2,0) + min(512 - y2, 0);
        g_box[0] = y1 + oy; g_box[1] = x1 + ox;
    }
}

// ---------------- copy pred->out + extract x/feat patches --------------------
__global__ void prep_kernel(const float* __restrict__ x,
                            const float* __restrict__ pred,
                            const float* __restrict__ feat,
                            float* __restrict__ out) {
    const int y1 = g_box[0], x1 = g_box[1];
    const int N1 = KB*3*PLANE;
    const int N2 = KB*3*NP;
    const int N3 = KB*64*NP;
    const int total = N1 + N2 + N3;
    for (int i = blockIdx.x * blockDim.x + threadIdx.x; i < total;
         i += gridDim.x * blockDim.x) {
        if (i < N1) {
            out[i] = pred[i];
        } else if (i < N1 + N2) {
            int j = i - N1;
            int kc = j / NP;
            int p  = j % NP;
            int yy = p >> 7, xx = p & 127;
            g_x_patch[j] = x[(size_t)kc * PLANE + (y1+yy)*512 + (x1+xx)];
        } else {
            int j = i - N1 - N2;
            int kc = j / NP;
            int p  = j % NP;
            int yy = p >> 7, xx = p & 127;
            g_feat_patch[j] = feat[(size_t)kc * PLANE + (y1+yy)*512 + (x1+xx)];
        }
    }
}

__global__ void extract_pred_kernel(const float* __restrict__ out) {
    int i = blockIdx.x * blockDim.x + threadIdx.x;
    if (i >= KB*3*NP) return;
    const int y1 = g_box[0], x1 = g_box[1];
    int kc = i / NP;
    int p  = i % NP;
    int yy = p >> 7, xx = p & 127;
    g_pred_patch[i] = out[(size_t)kc * PLANE + (y1+yy)*512 + (x1+xx)];
}

// ---------------- input loader modes -----------------------------------------
template<int MODE>
__device__ __forceinline__ float load_in(const float* __restrict__ in_base,
                                         int k, int cg, int gy, int gx) {
    int p = gy*P + gx;
    if (MODE == 2) {
        const float* f = in_base;              // g_fs + k*96*NP
        if (cg < 32) {
            return g_S1[cg*NP + p] / 5.0f - g_S0[cg*NP + p] + 2.0f * f[cg*NP + p];
        } else if (cg < 64) {
            int c = cg - 32;
            return g_S0[c*NP + p] - f[c*NP + p] + f[(32+c)*NP + p];
        } else if (cg < 96) {
            return g_M2[(cg-64)*NP + p];
        } else {
            return g_x_patch[(k*3 + (cg-96))*NP + p];
        }
    }
    return in_base[cg*NP + p];
}

// ---------------- register-tiled 3x3 conv body (f32x2 packed) ----------------
// Tile: 16 wide x 8 tall. Thread = 2x2 pixels x OCPT out channels
// (OCPT/2 packed channel-pairs). blockDim = (32, COUT/OCPT)
template<int CIN, int COUT, int OCPT, bool RELU, int MODE>
__device__ __forceinline__ void conv3x3_body(
    const float* __restrict__ in_base, int k,
    const float* __restrict__ att,
    const float* __restrict__ W,
    const float* __restrict__ Bv,
    float* __restrict__ out_base)
{
    constexpr int NOCG = COUT / OCPT;
    constexpr int NTHR = 32 * NOCG;
    constexpr int CCH  = 8;
    constexpr int NPR  = OCPT / 2;
    constexpr int WST  = COUT + 2;            // even stride: 8B-aligned, low conflict
    __shared__ float in_s[CCH][10][20];       // 18 valid cols, even stride 20
    __shared__ float w_t[CCH*9][WST];         // transposed: [c*9+kk][oc]
    __shared__ float att_s[10][20];

    const int x0 = blockIdx.x * 16;
    const int y0 = blockIdx.y * 8;
    const int tid = threadIdx.y * 32 + threadIdx.x;
    const int tx = (threadIdx.x & 7) * 2;
    const int ty = (threadIdx.x >> 3) * 2;
    const int ocb = threadIdx.y * OCPT;

    if (MODE == 1) {
        for (int i = tid; i < 180; i += NTHR) {
            int ly = i / 18, lx = i % 18;
            int gy = y0 + ly - 1, gx = x0 + lx - 1;
            att_s[ly][lx] = (gy >= 0 && gy < P && gx >= 0 && gx < P)
                                ? att[gy*P + gx] : 0.f;
        }
    }

    unsigned long long acc2[2][2][NPR];
    #pragma unroll
    for (int a = 0; a < 2; a++)
        #pragma unroll
        for (int b = 0; b < 2; b++)
            #pragma unroll
            for (int j = 0; j < NPR; j++) acc2[a][b][j] = 0ull;

    for (int c0 = 0; c0 < CIN; c0 += CCH) {
        __syncthreads();
        for (int i = tid; i < CCH*180; i += NTHR) {
            int c = i / 180, r = i % 180;
            int ly = r / 18, lx = r % 18;
            int gy = y0 + ly - 1, gx = x0 + lx - 1;
            int cg = c0 + c;
            float v = 0.f;
            if (cg < CIN && gy >= 0 && gy < P && gx >= 0 && gx < P) {
                v = load_in<MODE>(in_base, k, cg, gy, gx);
                if (MODE == 1) v *= att_s[ly][lx];
            }
            in_s[c][ly][lx] = v;
        }
        for (int i = tid; i < COUT*CCH*9; i += NTHR) {
            int o = i / (CCH*9), r = i % (CCH*9);
            int cg = c0 + r / 9, kk = r % 9;
            w_t[r][o] = (cg < CIN) ? W[(o*CIN + cg)*9 + kk] : 0.f;
        }
        __syncthreads();
        #pragma unroll 1
        for (int c = 0; c < CCH; c++) {
            // load 4x4 input window as LDS.64 pairs, duplicate each scalar once
            unsigned long long vd[4][4];
            #pragma unroll
            for (int dy = 0; dy < 4; dy++) {
                float2 a = *(const float2*)&in_s[c][ty+dy][tx];
                float2 b = *(const float2*)&in_s[c][ty+dy][tx+2];
                vd[dy][0] = dup2(a.x); vd[dy][1] = dup2(a.y);
                vd[dy][2] = dup2(b.x); vd[dy][3] = dup2(b.y);
            }
            #pragma unroll
            for (int kk = 0; kk < 9; kk++) {
                const int ky = kk / 3, kx = kk % 3;
                unsigned long long wp[NPR];
                #pragma unroll
                for (int jj = 0; jj < NPR; jj++)
                    wp[jj] = *(const unsigned long long*)&w_t[c*9+kk][ocb + 2*jj];
                #pragma unroll
                for (int py = 0; py < 2; py++)
                    #pragma unroll
                    for (int qx = 0; qx < 2; qx++) {
                        unsigned long long iv = vd[py+ky][qx+kx];
                        #pragma unroll
                        for (int jj = 0; jj < NPR; jj++)
                            fma2(acc2[py][qx][jj], iv, wp[jj]);
                    }
            }
        }
    }
    #pragma unroll
    for (int jj = 0; jj < NPR; jj++) {
        int o0 = ocb + 2*jj;
        float b0 = Bv[o0], b1 = Bv[o0+1];
        #pragma unroll
        for (int py = 0; py < 2; py++)
            #pragma unroll
            for (int qx = 0; qx < 2; qx++) {
                float2 rv = unpack2(acc2[py][qx][jj]);
                float r0 = rv.x + b0, r1 = rv.y + b1;
                if (RELU) {
                    r0 = (r0 >= 0.f) ? r0 : 0.2f * r0;
                    r1 = (r1 >= 0.f) ? r1 : 0.2f * r1;
                }
                int pix = (y0+ty+py)*P + (x0+tx+qx);
                out_base[o0*NP + pix]     = r0;
                out_base[(o0+1)*NP + pix] = r1;
            }
    }
}

__global__ void __launch_bounds__(128)
split_conv_kernel(const float* __restrict__ W, const float* __restrict__ Bv) {
    int z = blockIdx.z; int k = z / 3, g = z - 3*k;
    conv3x3_body<64, 32, 8, false, 1>(
        g_feat_patch + k*64*NP, k,
        g_pred_patch + (k*3 + g)*NP,
        W + g*32*64*9,
        Bv + g*32,
        g_fs + (k*96 + g*32)*NP);
}

__global__ void __launch_bounds__(256)
merge1_kernel(const float* __restrict__ W, const float* __restrict__ Bv) {
    int k = blockIdx.z;
    conv3x3_body<99, 64, 8, true, 2>(
        g_fs + k*96*NP, k, nullptr, W, Bv, g_h1 + k*64*NP);
}

__global__ void __launch_bounds__(256)
merge2_kernel(const float* __restrict__ W, const float* __restrict__ Bv) {
    int k = blockIdx.z;
    conv3x3_body<64, 64, 8, false, 0>(
        g_h1 + k*64*NP, k, nullptr, W, Bv, g_fm + k*64*NP);
}

// ---------------- K-reduction of fs ------------------------------------------
__global__ void reduce_kernel() {
    int i = blockIdx.x * blockDim.x + threadIdx.x;
    if (i >= 32*NP) return;
    int c = i / NP, p = i % NP;
    float s0 = 0.f, s1 = 0.f, s2 = 0.f;
    #pragma unroll
    for (int k = 0; k < KB; k++) {
        const float* f = g_fs + k*96*NP;
        s0 += f[c*NP + p];
        s1 += f[(32+c)*NP + p];
        s2 += f[(64+c)*NP + p];
    }
    g_S0[i] = s0; g_S1[i] = s1; g_M2[i] = s2 / 6.0f;
}

// ---------------- head conv + tanh + scatter ---------------------------------
__global__ void __launch_bounds__(256)
head_kernel(const float* __restrict__ W, const float* __restrict__ Bv,
            float* __restrict__ out) {
    __shared__ float in_s[8][18][20];
    __shared__ float w_s[3][72];
    const int k = blockIdx.z;
    const float* fm = g_fm + k*64*NP;
    const int x0 = blockIdx.x * 16, y0 = blockIdx.y * 16;
    const int tid = threadIdx.y * 16 + threadIdx.x;
    float acc[3] = {0.f, 0.f, 0.f};
    for (int c0 = 0; c0 < 64; c0 += 8) {
        __syncthreads();
        for (int i = tid; i < 8*18*18; i += 256) {
            int c = i / 324, r = i % 324, ly = r / 18, lx = r % 18;
            int gy = y0 + ly - 1, gx = x0 + lx - 1;
            in_s[c][ly][lx] = (gy >= 0 && gy < P && gx >= 0 && gx < P)
                                  ? fm[(c0+c)*NP + gy*P + gx] : 0.f;
        }
        for (int i = tid; i < 3*72; i += 256) {
            int o = i / 72, r = i % 72;
            int c = r / 9, kk = r % 9;
            w_s[o][r] = W[(o*64 + c0 + c)*9 + kk];
        }
        __syncthreads();
        #pragma unroll 1
        for (int c = 0; c < 8; c++) {
            #pragma unroll
            for (int kk = 0; kk < 9; kk++) {
                float v = in_s[c][threadIdx.y + kk/3][threadIdx.x + kk%3];
                #pragma unroll
                for (int o = 0; o < 3; o++)
                    acc[o] = fmaf(v, w_s[o][c*9+kk], acc[o]);
            }
        }
    }
    int y = y0 + threadIdx.y, x = x0 + threadIdx.x;
    if (y >= 10 && y < 118 && x >= 10 && x < 118) {
        int y1 = g_box[0], x1 = g_box[1];
        #pragma unroll
        for (int o = 0; o < 3; o++) {
            float val = 0.5f * (tanhf(acc[o] + Bv[o]) + 1.0f);
            out[(size_t)(k*3 + o) * PLANE + (y1+y)*512 + (x1+x)] = val;
        }
    }
}

// ---------------- launch -----------------------------------------------------
extern "C" void kernel_launch(void* const* d_in, const int* in_sizes, int n_in,
                              void* d_out, int out_size) {
    const float* x       = (const float*)d_in[0];
    const float* pred    = (const float*)d_in[1];
    const float* feat    = (const float*)d_in[2];
    const float* split_w = (const float*)d_in[3];
    const float* split_b = (const float*)d_in[4];
    const float* m1w     = (const float*)d_in[5];
    const float* m1b     = (const float*)d_in[6];
    const float* m2w     = (const float*)d_in[7];
    const float* m2b     = (const float*)d_in[8];
    const float* hw      = (const float*)d_in[9];
    const float* hb      = (const float*)d_in[10];
    float* out = (float*)d_out;

    box_kernel<<<1, 1024>>>(pred);
    prep_kernel<<<8192, 256>>>(x, pred, feat, out);

    dim3 gridM(8, 16, KB),   blkM(32, 8);
    dim3 gridS(8, 16, KB*3), blkS(32, 4);
    dim3 gridH(8, 8, KB),    blkH(16, 16);

    for (int it = 0; it < 2; it++) {
        extract_pred_kernel<<<(KB*3*NP + 255)/256, 256>>>(out);
        split_conv_kernel<<<gridS, blkS>>>(split_w, split_b);
        reduce_kernel<<<(32*NP + 255)/256, 256>>>();
        merge1_kernel<<<gridM, blkM>>>(m1w, m1b);
        merge2_kernel<<<gridM, blkM>>>(m2w, m2b);
        head_kernel<<<gridH, blkH>>>(hw, hb, out);
    }
}

// round 5
// speedup vs baseline: 1.3142x; 1.0322x over previous
#include <cuda_runtime.h>
#include <math.h>

#define P 128
#define NP 16384          // 128*128
#define KB 6
#define PLANE 262144      // 512*512

// ---------------- scratch (static device globals; no allocation) -------------
__device__ int   g_box[2];                     // y1, x1
__device__ float g_feat_patch[KB*64*NP];
__device__ float g_x_patch[KB*3*NP];
__device__ float g_pred_patch[KB*3*NP];
__device__ float g_fs[KB*96*NP];
__device__ float g_S0[32*NP];
__device__ float g_S1[32*NP];
__device__ float g_M2[32*NP];
__device__ float g_h1[KB*64*NP];
__device__ float g_fm[KB*64*NP];

// ---------------- packed f32x2 helpers ---------------------------------------
__device__ __forceinline__ unsigned long long dup2(float v) {
    unsigned long long r;
    asm("mov.b64 %0, {%1, %1};" : "=l"(r) : "f"(v));
    return r;
}
__device__ __forceinline__ void fma2(unsigned long long& d,
                                     unsigned long long a,
                                     unsigned long long b) {
    asm("fma.rn.f32x2 %0, %1, %2, %0;" : "+l"(d) : "l"(a), "l"(b));
}
__device__ __forceinline__ float2 unpack2(unsigned long long v) {
    float2 f;
    asm("mov.b64 {%0, %1}, %2;" : "=f"(f.x), "=f"(f.y) : "l"(v));
    return f;
}

// ---------------- box computation -------------------------------------------
__global__ void box_kernel(const float* __restrict__ pred) {
    __shared__ float svals[1024];
    __shared__ int   sidx[1024];
    const int t = threadIdx.x;
    float best = -1e30f; int bidx = 0;
    for (int i = t; i < 51*51; i += 1024) {
        int iy = i / 51, ix = i % 51;
        int y = iy * 10, x = ix * 10;
        float T = 0.f, Bm = 0.f;
        for (int k = 0; k < KB; k++) {
            const float* pk = pred + (size_t)k * 3 * PLANE + y * 512 + x;
            T  += pk[0];
            Bm += pk[2*PLANE];
        }
        float d = fabsf(1.0f - T - Bm / 6.0f);
        if (d > best) { best = d; bidx = i; }
    }
    svals[t] = best; sidx[t] = bidx;
    __syncthreads();
    for (int s = 512; s > 0; s >>= 1) {
        if (t < s) {
            if (svals[t+s] > svals[t] ||
                (svals[t+s] == svals[t] && sidx[t+s] < sidx[t])) {
                svals[t] = svals[t+s]; sidx[t] = sidx[t+s];
            }
        }
        __syncthreads();
    }
    if (t == 0) {
        int idx = sidx[0];
        int cx = (idx % 51) * 10, cy = (idx / 51) * 10;
        int x1 = cx - 64, y1 = cy - 64, x2 = cx + 64, y2 = cy + 64;
        int ox = -min(x1,0) + min(512 - x1, 0) - min(x2,0) + min(512 - x2, 0);
        int oy = -min(y1,0) + min(512 - y1, 0) - min(y2,0) + min(512 - y2, 0);
        g_box[0] = y1 + oy; g_box[1] = x1 + ox;
    }
}

// ---------------- copy pred->out + extract x/feat patches --------------------
__global__ void prep_kernel(const float* __restrict__ x,
                            const float* __restrict__ pred,
                            const float* __restrict__ feat,
                            float* __restrict__ out) {
    const int y1 = g_box[0], x1 = g_box[1];
    const int N1 = KB*3*PLANE;
    const int N2 = KB*3*NP;
    const int N3 = KB*64*NP;
    const int total = N1 + N2 + N3;
    for (int i = blockIdx.x * blockDim.x + threadIdx.x; i < total;
         i += gridDim.x * blockDim.x) {
        if (i < N1) {
            out[i] = pred[i];
        } else if (i < N1 + N2) {
            int j = i - N1;
            int kc = j / NP;
            int p  = j % NP;
            int yy = p >> 7, xx = p & 127;
            g_x_patch[j] = x[(size_t)kc * PLANE + (y1+yy)*512 + (x1+xx)];
        } else {
            int j = i - N1 - N2;
            int kc = j / NP;
            int p  = j % NP;
            int yy = p >> 7, xx = p & 127;
            g_feat_patch[j] = feat[(size_t)kc * PLANE + (y1+yy)*512 + (x1+xx)];
        }
    }
}

__global__ void extract_pred_kernel(const float* __restrict__ out) {
    int i = blockIdx.x * blockDim.x + threadIdx.x;
    if (i >= KB*3*NP) return;
    const int y1 = g_box[0], x1 = g_box[1];
    int kc = i / NP;
    int p  = i % NP;
    int yy = p >> 7, xx = p & 127;
    g_pred_patch[i] = out[(size_t)kc * PLANE + (y1+yy)*512 + (x1+xx)];
}

// ---------------- input loader modes -----------------------------------------
template<int MODE>
__device__ __forceinline__ float load_in(const float* __restrict__ in_base,
                                         int k, int cg, int gy, int gx) {
    int p = gy*P + gx;
    if (MODE == 2) {
        const float* f = in_base;              // g_fs + k*96*NP
        if (cg < 32) {
            return g_S1[cg*NP + p] / 5.0f - g_S0[cg*NP + p] + 2.0f * f[cg*NP + p];
        } else if (cg < 64) {
            int c = cg - 32;
            return g_S0[c*NP + p] - f[c*NP + p] + f[(32+c)*NP + p];
        } else if (cg < 96) {
            return g_M2[(cg-64)*NP + p];
        } else {
            return g_x_patch[(k*3 + (cg-96))*NP + p];
        }
    }
    return in_base[cg*NP + p];
}

// ---------------- register-tiled 3x3 conv body (f32x2 packed) ----------------
// Tile: 16 wide x 8 tall. Thread = 2x2 pixels x OCPT out channels
// (OCPT/2 packed channel-pairs). blockDim = (32, COUT/OCPT)
template<int CIN, int COUT, int OCPT, bool RELU, int MODE>
__device__ __forceinline__ void conv3x3_body(
    const float* __restrict__ in_base, int k,
    const float* __restrict__ att,
    const float* __restrict__ W,
    const float* __restrict__ Bv,
    float* __restrict__ out_base)
{
    constexpr int NOCG = COUT / OCPT;
    constexpr int NTHR = 32 * NOCG;
    constexpr int CCH  = 8;
    constexpr int NPR  = OCPT / 2;
    constexpr int WST  = COUT + 2;            // even stride: 8B-aligned, low conflict
    __shared__ float in_s[CCH][10][20];       // 18 valid cols, even stride 20
    __shared__ float w_t[CCH*9][WST];         // transposed: [c*9+kk][oc]
    __shared__ float att_s[10][20];

    const int x0 = blockIdx.x * 16;
    const int y0 = blockIdx.y * 8;
    const int tid = threadIdx.y * 32 + threadIdx.x;
    const int tx = (threadIdx.x & 7) * 2;
    const int ty = (threadIdx.x >> 3) * 2;
    const int ocb = threadIdx.y * OCPT;

    if (MODE == 1) {
        for (int i = tid; i < 180; i += NTHR) {
            int ly = i / 18, lx = i % 18;
            int gy = y0 + ly - 1, gx = x0 + lx - 1;
            att_s[ly][lx] = (gy >= 0 && gy < P && gx >= 0 && gx < P)
                                ? att[gy*P + gx] : 0.f;
        }
    }

    unsigned long long acc2[2][2][NPR];
    #pragma unroll
    for (int a = 0; a < 2; a++)
        #pragma unroll
        for (int b = 0; b < 2; b++)
            #pragma unroll
            for (int j = 0; j < NPR; j++) acc2[a][b][j] = 0ull;

    for (int c0 = 0; c0 < CIN; c0 += CCH) {
        __syncthreads();
        for (int i = tid; i < CCH*180; i += NTHR) {
            int c = i / 180, r = i % 180;
            int ly = r / 18, lx = r % 18;
            int gy = y0 + ly - 1, gx = x0 + lx - 1;
            int cg = c0 + c;
            float v = 0.f;
            if (cg < CIN && gy >= 0 && gy < P && gx >= 0 && gx < P) {
                v = load_in<MODE>(in_base, k, cg, gy, gx);
                if (MODE == 1) v *= att_s[ly][lx];
            }
            in_s[c][ly][lx] = v;
        }
        for (int i = tid; i < COUT*CCH*9; i += NTHR) {
            int o = i / (CCH*9), r = i % (CCH*9);
            int cg = c0 + r / 9, kk = r % 9;
            w_t[r][o] = (cg < CIN) ? W[(o*CIN + cg)*9 + kk] : 0.f;
        }
        __syncthreads();
        // FULLY UNROLLED: c and kk become compile-time constants so all LDS
        // addresses fold into immediate offsets (no per-access IMAD), and the
        // scheduler can pipeline LDS.64 across channel iterations.
        #pragma unroll
        for (int c = 0; c < CCH; c++) {
            unsigned long long vd[4][4];
            #pragma unroll
            for (int dy = 0; dy < 4; dy++) {
                float2 a = *(const float2*)&in_s[c][ty+dy][tx];
                float2 b = *(const float2*)&in_s[c][ty+dy][tx+2];
                vd[dy][0] = dup2(a.x); vd[dy][1] = dup2(a.y);
                vd[dy][2] = dup2(b.x); vd[dy][3] = dup2(b.y);
            }
            #pragma unroll
            for (int kk = 0; kk < 9; kk++) {
                const int ky = kk / 3, kx = kk % 3;
                unsigned long long wp[NPR];
                #pragma unroll
                for (int jj = 0; jj < NPR; jj++)
                    wp[jj] = *(const unsigned long long*)&w_t[c*9+kk][ocb + 2*jj];
                #pragma unroll
                for (int py = 0; py < 2; py++)
                    #pragma unroll
                    for (int qx = 0; qx < 2; qx++) {
                        unsigned long long iv = vd[py+ky][qx+kx];
                        #pragma unroll
                        for (int jj = 0; jj < NPR; jj++)
                            fma2(acc2[py][qx][jj], iv, wp[jj]);
                    }
            }
        }
    }
    #pragma unroll
    for (int jj = 0; jj < NPR; jj++) {
        int o0 = ocb + 2*jj;
        float b0 = Bv[o0], b1 = Bv[o0+1];
        #pragma unroll
        for (int py = 0; py < 2; py++)
            #pragma unroll
            for (int qx = 0; qx < 2; qx++) {
                float2 rv = unpack2(acc2[py][qx][jj]);
                float r0 = rv.x + b0, r1 = rv.y + b1;
                if (RELU) {
                    r0 = (r0 >= 0.f) ? r0 : 0.2f * r0;
                    r1 = (r1 >= 0.f) ? r1 : 0.2f * r1;
                }
                int pix = (y0+ty+py)*P + (x0+tx+qx);
                out_base[o0*NP + pix]     = r0;
                out_base[(o0+1)*NP + pix] = r1;
            }
    }
}

__global__ void __launch_bounds__(128)
split_conv_kernel(const float* __restrict__ W, const float* __restrict__ Bv) {
    int z = blockIdx.z; int k = z / 3, g = z - 3*k;
    conv3x3_body<64, 32, 8, false, 1>(
        g_feat_patch + k*64*NP, k,
        g_pred_patch + (k*3 + g)*NP,
        W + g*32*64*9,
        Bv + g*32,
        g_fs + (k*96 + g*32)*NP);
}

__global__ void __launch_bounds__(256)
merge1_kernel(const float* __restrict__ W, const float* __restrict__ Bv) {
    int k = blockIdx.z;
    conv3x3_body<99, 64, 8, true, 2>(
        g_fs + k*96*NP, k, nullptr, W, Bv, g_h1 + k*64*NP);
}

__global__ void __launch_bounds__(256)
merge2_kernel(const float* __restrict__ W, const float* __restrict__ Bv) {
    int k = blockIdx.z;
    conv3x3_body<64, 64, 8, false, 0>(
        g_h1 + k*64*NP, k, nullptr, W, Bv, g_fm + k*64*NP);
}

// ---------------- K-reduction of fs ------------------------------------------
__global__ void reduce_kernel() {
    int i = blockIdx.x * blockDim.x + threadIdx.x;
    if (i >= 32*NP) return;
    int c = i / NP, p = i % NP;
    float s0 = 0.f, s1 = 0.f, s2 = 0.f;
    #pragma unroll
    for (int k = 0; k < KB; k++) {
        const float* f = g_fs + k*96*NP;
        s0 += f[c*NP + p];
        s1 += f[(32+c)*NP + p];
        s2 += f[(64+c)*NP + p];
    }
    g_S0[i] = s0; g_S1[i] = s1; g_M2[i] = s2 / 6.0f;
}

// ---------------- head conv + tanh + scatter ---------------------------------
__global__ void __launch_bounds__(256)
head_kernel(const float* __restrict__ W, const float* __restrict__ Bv,
            float* __restrict__ out) {
    __shared__ float in_s[8][18][20];
    __shared__ float w_s[3][72];
    const int k = blockIdx.z;
    const float* fm = g_fm + k*64*NP;
    const int x0 = blockIdx.x * 16, y0 = blockIdx.y * 16;
    const int tid = threadIdx.y * 16 + threadIdx.x;
    float acc[3] = {0.f, 0.f, 0.f};
    for (int c0 = 0; c0 < 64; c0 += 8) {
        __syncthreads();
        for (int i = tid; i < 8*18*18; i += 256) {
            int c = i / 324, r = i % 324, ly = r / 18, lx = r % 18;
            int gy = y0 + ly - 1, gx = x0 + lx - 1;
            in_s[c][ly][lx] = (gy >= 0 && gy < P && gx >= 0 && gx < P)
                                  ? fm[(c0+c)*NP + gy*P + gx] : 0.f;
        }
        for (int i = tid; i < 3*72; i += 256) {
            int o = i / 72, r = i % 72;
            int c = r / 9, kk = r % 9;
            w_s[o][r] = W[(o*64 + c0 + c)*9 + kk];
        }
        __syncthreads();
        #pragma unroll
        for (int c = 0; c < 8; c++) {
            #pragma unroll
            for (int kk = 0; kk < 9; kk++) {
                float v = in_s[c][threadIdx.y + kk/3][threadIdx.x + kk%3];
                #pragma unroll
                for (int o = 0; o < 3; o++)
                    acc[o] = fmaf(v, w_s[o][c*9+kk], acc[o]);
            }
        }
    }
    int y = y0 + threadIdx.y, x = x0 + threadIdx.x;
    if (y >= 10 && y < 118 && x >= 10 && x < 118) {
        int y1 = g_box[0], x1 = g_box[1];
        #pragma unroll
        for (int o = 0; o < 3; o++) {
            float val = 0.5f * (tanhf(acc[o] + Bv[o]) + 1.0f);
            out[(size_t)(k*3 + o) * PLANE + (y1+y)*512 + (x1+x)] = val;
        }
    }
}

// ---------------- launch -----------------------------------------------------
extern "C" void kernel_launch(void* const* d_in, const int* in_sizes, int n_in,
                              void* d_out, int out_size) {
    const float* x       = (const float*)d_in[0];
    const float* pred    = (const float*)d_in[1];
    const float* feat    = (const float*)d_in[2];
    const float* split_w = (const float*)d_in[3];
    const float* split_b = (const float*)d_in[4];
    const float* m1w     = (const float*)d_in[5];
    const float* m1b     = (const float*)d_in[6];
    const float* m2w     = (const float*)d_in[7];
    const float* m2b     = (const float*)d_in[8];
    const float* hw      = (const float*)d_in[9];
    const float* hb      = (const float*)d_in[10];
    float* out = (float*)d_out;

    box_kernel<<<1, 1024>>>(pred);
    prep_kernel<<<8192, 256>>>(x, pred, feat, out);

    dim3 gridM(8, 16, KB),   blkM(32, 8);
    dim3 gridS(8, 16, KB*3), blkS(32, 4);
    dim3 gridH(8, 8, KB),    blkH(16, 16);

    for (int it = 0; it < 2; it++) {
        extract_pred_kernel<<<(KB*3*NP + 255)/256, 256>>>(out);
        split_conv_kernel<<<gridS, blkS>>>(split_w, split_b);
        reduce_kernel<<<(32*NP + 255)/256, 256>>>();
        merge1_kernel<<<gridM, blkM>>>(m1w, m1b);
        merge2_kernel<<<gridM, blkM>>>(m2w, m2b);
        head_kernel<<<gridH, blkH>>>(hw, hb, out);
    }
}